// round 1
// baseline (speedup 1.0000x reference)
#include <cuda_runtime.h>
#include <cstdint>

// AddRadiusEdgeIndex: pairwise squared distances + radius mask, N=8192, r=1.
// Output: [N*N] masked_dist2 (f32), then [N*N] edge_mask as 0.0/1.0 (f32).
//
// Numerics deliberately replicate the reference:
//   sq[i]  = x*x + y*y + z*z          (plain mul/add, no FMA contraction)
//   dot    = fma(z, z', fma(y, y', x*x))   (FMA chain, gemm-like)
//   d2     = (sq_i + sq_j) - 2*dot ;  d2 = max(d2, 0) ; mask = d2 <= 1

#define TI 64
#define TJ 128
#define R2 1.0f

__global__ __launch_bounds__(256, 4)
void radius_edge_kernel(const float* __restrict__ pos,
                        float* __restrict__ dist_out,
                        float* __restrict__ mask_out,
                        int n)
{
    __shared__ float jx[TJ], jy[TJ], jz[TJ], jsq[TJ];
    __shared__ float ix[TI], iy[TI], iz[TI], isq[TI];

    const int j0 = blockIdx.x * TJ;
    const int i0 = blockIdx.y * TI;
    const int t  = threadIdx.x;   // 256 threads

    // Stage tiles. sq uses plain mul/add rounding (matches jnp.sum(pos*pos)).
    if (t < TJ) {
        int j = j0 + t;
        float x = pos[3 * j + 0];
        float y = pos[3 * j + 1];
        float z = pos[3 * j + 2];
        jx[t] = x; jy[t] = y; jz[t] = z;
        jsq[t] = __fadd_rn(__fadd_rn(__fmul_rn(x, x), __fmul_rn(y, y)),
                           __fmul_rn(z, z));
    } else if (t < TJ + TI) {
        int i = i0 + (t - TJ);
        float x = pos[3 * i + 0];
        float y = pos[3 * i + 1];
        float z = pos[3 * i + 2];
        ix[t - TJ] = x; iy[t - TJ] = y; iz[t - TJ] = z;
        isq[t - TJ] = __fadd_rn(__fadd_rn(__fmul_rn(x, x), __fmul_rn(y, y)),
                                __fmul_rn(z, z));
    }
    __syncthreads();

    // Thread layout: tx in [0,32) -> j-quad, ty in [0,8) -> i stride.
    const int tx = t & 31;
    const int ty = t >> 5;
    const int jj = tx * 4;            // local j base (4 consecutive)

    // Pull the j-quad into registers once.
    float xj0 = jx[jj + 0], xj1 = jx[jj + 1], xj2 = jx[jj + 2], xj3 = jx[jj + 3];
    float yj0 = jy[jj + 0], yj1 = jy[jj + 1], yj2 = jy[jj + 2], yj3 = jy[jj + 3];
    float zj0 = jz[jj + 0], zj1 = jz[jj + 1], zj2 = jz[jj + 2], zj3 = jz[jj + 3];
    float sj0 = jsq[jj + 0], sj1 = jsq[jj + 1], sj2 = jsq[jj + 2], sj3 = jsq[jj + 3];

    const size_t col = (size_t)(j0 + jj);
    const size_t nn  = (size_t)n * (size_t)n;

#pragma unroll
    for (int k = 0; k < TI / 8; ++k) {
        const int il = ty + k * 8;            // local i
        const float xi = ix[il], yi = iy[il], zi = iz[il], si = isq[il];

        // dot via FMA chain (gemm-like), then d2 = (si+sj) - 2*dot, clamp.
        float d0, d1, d2v, d3;
        {
            float dt = __fmaf_rn(zi, zj0, __fmaf_rn(yi, yj0, __fmul_rn(xi, xj0)));
            d0 = __fsub_rn(__fadd_rn(si, sj0), __fadd_rn(dt, dt));
        }
        {
            float dt = __fmaf_rn(zi, zj1, __fmaf_rn(yi, yj1, __fmul_rn(xi, xj1)));
            d1 = __fsub_rn(__fadd_rn(si, sj1), __fadd_rn(dt, dt));
        }
        {
            float dt = __fmaf_rn(zi, zj2, __fmaf_rn(yi, yj2, __fmul_rn(xi, xj2)));
            d2v = __fsub_rn(__fadd_rn(si, sj2), __fadd_rn(dt, dt));
        }
        {
            float dt = __fmaf_rn(zi, zj3, __fmaf_rn(yi, yj3, __fmul_rn(xi, xj3)));
            d3 = __fsub_rn(__fadd_rn(si, sj3), __fadd_rn(dt, dt));
        }
        d0 = fmaxf(d0, 0.0f);
        d1 = fmaxf(d1, 0.0f);
        d2v = fmaxf(d2v, 0.0f);
        d3 = fmaxf(d3, 0.0f);

        const float m0 = (d0 <= R2) ? 1.0f : 0.0f;
        const float m1 = (d1 <= R2) ? 1.0f : 0.0f;
        const float m2 = (d2v <= R2) ? 1.0f : 0.0f;
        const float m3 = (d3 <= R2) ? 1.0f : 0.0f;

        float4 dist4;
        dist4.x = m0 != 0.0f ? d0 : 0.0f;
        dist4.y = m1 != 0.0f ? d1 : 0.0f;
        dist4.z = m2 != 0.0f ? d2v : 0.0f;
        dist4.w = m3 != 0.0f ? d3 : 0.0f;

        const size_t off = (size_t)(i0 + il) * (size_t)n + col;
        *reinterpret_cast<float4*>(dist_out + off) = dist4;

        if (mask_out != nullptr) {
            float4 mask4 = make_float4(m0, m1, m2, m3);
            *reinterpret_cast<float4*>(mask_out + off) = mask4;
        }
        (void)nn;
    }
}

extern "C" void kernel_launch(void* const* d_in, const int* in_sizes, int n_in,
                              void* d_out, int out_size)
{
    const float* pos = (const float*)d_in[0];
    const int n = in_sizes[0] / 3;           // 8192

    float* out  = (float*)d_out;
    float* dist = out;
    const long long nn = (long long)n * (long long)n;
    float* mask = ((long long)out_size >= 2 * nn) ? (out + (size_t)nn) : nullptr;

    dim3 grid((n + TJ - 1) / TJ, (n + TI - 1) / TI);
    radius_edge_kernel<<<grid, 256>>>(pos, dist, mask, n);
}

// round 2
// speedup vs baseline: 1.0004x; 1.0004x over previous
#include <cuda_runtime.h>
#include <cstdint>

// AddRadiusEdgeIndex: pairwise squared distances + radius mask, N=8192, r=1.
// Output: [N*N] masked_dist2 (f32), then [N*N] edge_mask as 0.0/1.0 (f32).
//
// Numerics deliberately replicate the reference bit-exactly:
//   sq[i]  = x*x + y*y + z*z                (plain mul/add, no FMA contraction)
//   dot    = fma(z, z', fma(y, y', x*x))    (FMA chain, gemm-like)
//   d2     = (sq_i + sq_j) - 2*dot ;  d2 = max(d2, 0) ; mask = d2 <= 1
//
// HBM-store-bound: 512 MB written per launch. Tile reshaped to 32 rows x 256
// cols (1 KB contiguous per row) and stores use .cs (evict-streaming).

#define TI 32
#define TJ 256
#define R2 1.0f

__global__ __launch_bounds__(256, 4)
void radius_edge_kernel(const float* __restrict__ pos,
                        float* __restrict__ dist_out,
                        float* __restrict__ mask_out,
                        int n)
{
    __shared__ float jx[TJ], jy[TJ], jz[TJ], jsq[TJ];
    __shared__ float ix[TI], iy[TI], iz[TI], isq[TI];

    const int j0 = blockIdx.x * TJ;
    const int i0 = blockIdx.y * TI;
    const int t  = threadIdx.x;   // 256 threads

    // Stage tiles. sq uses plain mul/add rounding (matches jnp.sum(pos*pos)).
    {
        int j = j0 + t;           // t covers all TJ=256
        float x = pos[3 * j + 0];
        float y = pos[3 * j + 1];
        float z = pos[3 * j + 2];
        jx[t] = x; jy[t] = y; jz[t] = z;
        jsq[t] = __fadd_rn(__fadd_rn(__fmul_rn(x, x), __fmul_rn(y, y)),
                           __fmul_rn(z, z));
    }
    if (t < TI) {
        int i = i0 + t;
        float x = pos[3 * i + 0];
        float y = pos[3 * i + 1];
        float z = pos[3 * i + 2];
        ix[t] = x; iy[t] = y; iz[t] = z;
        isq[t] = __fadd_rn(__fadd_rn(__fmul_rn(x, x), __fmul_rn(y, y)),
                           __fmul_rn(z, z));
    }
    __syncthreads();

    // Thread layout: tx in [0,64) -> j-quad (4 consecutive j), ty in [0,4).
    const int tx = t & 63;
    const int ty = t >> 6;
    const int jj = tx * 4;

    // Pull the j-quad into registers once.
    const float xj0 = jx[jj + 0], xj1 = jx[jj + 1], xj2 = jx[jj + 2], xj3 = jx[jj + 3];
    const float yj0 = jy[jj + 0], yj1 = jy[jj + 1], yj2 = jy[jj + 2], yj3 = jy[jj + 3];
    const float zj0 = jz[jj + 0], zj1 = jz[jj + 1], zj2 = jz[jj + 2], zj3 = jz[jj + 3];
    const float sj0 = jsq[jj + 0], sj1 = jsq[jj + 1], sj2 = jsq[jj + 2], sj3 = jsq[jj + 3];

    const size_t col = (size_t)(j0 + jj);

#pragma unroll
    for (int k = 0; k < TI / 4; ++k) {
        const int il = ty + k * 4;            // local i (0..31)
        const float xi = ix[il], yi = iy[il], zi = iz[il], si = isq[il];

        float d0, d1, d2v, d3;
        {
            float dt = __fmaf_rn(zi, zj0, __fmaf_rn(yi, yj0, __fmul_rn(xi, xj0)));
            d0 = __fsub_rn(__fadd_rn(si, sj0), __fadd_rn(dt, dt));
        }
        {
            float dt = __fmaf_rn(zi, zj1, __fmaf_rn(yi, yj1, __fmul_rn(xi, xj1)));
            d1 = __fsub_rn(__fadd_rn(si, sj1), __fadd_rn(dt, dt));
        }
        {
            float dt = __fmaf_rn(zi, zj2, __fmaf_rn(yi, yj2, __fmul_rn(xi, xj2)));
            d2v = __fsub_rn(__fadd_rn(si, sj2), __fadd_rn(dt, dt));
        }
        {
            float dt = __fmaf_rn(zi, zj3, __fmaf_rn(yi, yj3, __fmul_rn(xi, xj3)));
            d3 = __fsub_rn(__fadd_rn(si, sj3), __fadd_rn(dt, dt));
        }
        d0  = fmaxf(d0, 0.0f);
        d1  = fmaxf(d1, 0.0f);
        d2v = fmaxf(d2v, 0.0f);
        d3  = fmaxf(d3, 0.0f);

        const float m0 = (d0  <= R2) ? 1.0f : 0.0f;
        const float m1 = (d1  <= R2) ? 1.0f : 0.0f;
        const float m2 = (d2v <= R2) ? 1.0f : 0.0f;
        const float m3 = (d3  <= R2) ? 1.0f : 0.0f;

        float4 dist4;
        dist4.x = m0 != 0.0f ? d0  : 0.0f;
        dist4.y = m1 != 0.0f ? d1  : 0.0f;
        dist4.z = m2 != 0.0f ? d2v : 0.0f;
        dist4.w = m3 != 0.0f ? d3  : 0.0f;

        const size_t off = (size_t)(i0 + il) * (size_t)n + col;
        __stcs(reinterpret_cast<float4*>(dist_out + off), dist4);

        if (mask_out != nullptr) {
            __stcs(reinterpret_cast<float4*>(mask_out + off),
                   make_float4(m0, m1, m2, m3));
        }
    }
}

extern "C" void kernel_launch(void* const* d_in, const int* in_sizes, int n_in,
                              void* d_out, int out_size)
{
    const float* pos = (const float*)d_in[0];
    const int n = in_sizes[0] / 3;           // 8192

    float* out  = (float*)d_out;
    float* dist = out;
    const long long nn = (long long)n * (long long)n;
    float* mask = ((long long)out_size >= 2 * nn) ? (out + (size_t)nn) : nullptr;

    dim3 grid((n + TJ - 1) / TJ, (n + TI - 1) / TI);
    radius_edge_kernel<<<grid, 256>>>(pos, dist, mask, n);
}